// round 13
// baseline (speedup 1.0000x reference)
#include <cuda_runtime.h>
#include <cuda_fp16.h>
#include <stdint.h>

// ---------------- problem constants ----------------
constexpr int B = 2, H = 16, S = 2048, D = 64;
constexpr int BH = B * H;
// fold 1/T and log2(e) into Q so exp(s) == exp2(score)
constexpr float SCALE = 1.4426950408889634f / 32.0f;

constexpr int QT = 16;            // query rows per CTA
constexpr int THREADS = 256;      // 8 warps; warp j owns keys [256j, 256j+256)

// smem layout (bytes)
// [0, 65536)      : 8 warps x 2 x 4KB private K/V streaming buffers; reused as O slabs
// [65536, 73728)  : mask bias (2048 floats)
// [73728, 74240)  : row-sum table [16][8]
// [74240, 74304)  : per-row inverse [16]
constexpr int SM_BUF  = 0;
constexpr int SM_MASK = 65536;
constexpr int SM_RST  = SM_MASK + 8192;
constexpr int SM_INV  = SM_RST + 512;
constexpr int SMEM_SZ = SM_INV + 64;      // 74304 -> 2 CTAs/SM

// ---------------- device fp16 copies ----------------
__device__ __half g_q16[(size_t)BH * S * D];
__device__ __half g_k16[(size_t)BH * S * D];
__device__ __half g_v16[(size_t)BH * S * D];

// ---------------- helpers ----------------
__device__ __forceinline__ uint32_t su32(const void* p) {
    uint32_t a;
    asm("{ .reg .u64 t; cvta.to.shared.u64 t, %1; cvt.u32.u64 %0, t; }" : "=r"(a) : "l"(p));
    return a;
}
__device__ __forceinline__ void cpa16(uint32_t d, const void* s) {
    asm volatile("cp.async.cg.shared.global [%0], [%1], 16;" :: "r"(d), "l"(s));
}
#define CP_COMMIT() asm volatile("cp.async.commit_group;" ::: "memory")
#define CP_WAIT0()  asm volatile("cp.async.wait_group 0;" ::: "memory")
#define CP_WAIT1()  asm volatile("cp.async.wait_group 1;" ::: "memory")

#define LDSM4(r0, r1, r2, r3, a) \
    asm volatile("ldmatrix.sync.aligned.m8n8.x4.shared.b16 {%0,%1,%2,%3}, [%4];" \
                 : "=r"(r0), "=r"(r1), "=r"(r2), "=r"(r3) : "r"(a))
#define LDSM4T(r0, r1, r2, r3, a) \
    asm volatile("ldmatrix.sync.aligned.m8n8.x4.trans.shared.b16 {%0,%1,%2,%3}, [%4];" \
                 : "=r"(r0), "=r"(r1), "=r"(r2), "=r"(r3) : "r"(a))

__device__ __forceinline__ void mma_f16(float4& c, const uint32_t* a,
                                        uint32_t b0, uint32_t b1) {
    asm volatile(
        "mma.sync.aligned.m16n8k16.row.col.f32.f16.f16.f32 "
        "{%0,%1,%2,%3}, {%4,%5,%6,%7}, {%8,%9}, {%0,%1,%2,%3};"
        : "+f"(c.x), "+f"(c.y), "+f"(c.z), "+f"(c.w)
        : "r"(a[0]), "r"(a[1]), "r"(a[2]), "r"(a[3]), "r"(b0), "r"(b1));
}
__device__ __forceinline__ uint32_t packh2(float a, float b) {
    __half2 h = __floats2half2_rn(a, b);
    return *(uint32_t*)&h;
}
__device__ __forceinline__ float2 unpackh2(uint32_t u) {
    return __half22float2(*(__half2*)&u);
}
__device__ __forceinline__ float2 shfl_xor_f2(float2 v, int m) {
    v.x = __shfl_xor_sync(0xffffffffu, v.x, m);
    v.y = __shfl_xor_sync(0xffffffffu, v.y, m);
    return v;
}
// 4x4 transpose of float2 a[4] across a quad of lanes (q = lane&3).
__device__ __forceinline__ void quad_transpose_f2(float2 a[4], int q) {
    {
        float2 v = (q & 1) ? a[0] : a[1];
        v = shfl_xor_f2(v, 1);
        if (q & 1) a[0] = v; else a[1] = v;
        float2 u = (q & 1) ? a[2] : a[3];
        u = shfl_xor_f2(u, 1);
        if (q & 1) a[2] = u; else a[3] = u;
    }
    {
        float2 v = (q & 2) ? a[0] : a[2];
        v = shfl_xor_f2(v, 2);
        if (q & 2) a[0] = v; else a[2] = v;
        float2 u = (q & 2) ? a[1] : a[3];
        u = shfl_xor_f2(u, 2);
        if (q & 2) a[1] = u; else a[3] = u;
    }
}

// 32-key chunk (32 rows x 128B, XOR-swizzled) loaded by ONE warp (8 cp.async/lane)
__device__ __forceinline__ void load_chunk(uint32_t dst, const __half* g, int L) {
#pragma unroll
    for (int it = 0; it < 8; it++) {
        int f = L + it * 32;
        int r = f >> 3, c = f & 7;
        cpa16(dst + r * 128 + ((c ^ (r & 7)) << 4), g + r * 64 + c * 8);
    }
}

// ---------------- prep: fp32 -> fp16 (Q scaled by log2e/T) ----------------
__global__ void prep16(const float* __restrict__ q, const float* __restrict__ k,
                       const float* __restrict__ v) {
    const int N4 = BH * S * D / 4;
    int i = blockIdx.x * blockDim.x + threadIdx.x;
    if (i >= N4) return;
    float4 a = ((const float4*)q)[i];
    float4 b = ((const float4*)k)[i];
    float4 c = ((const float4*)v)[i];
    __half2* q2 = (__half2*)g_q16;
    __half2* k2 = (__half2*)g_k16;
    __half2* v2 = (__half2*)g_v16;
    q2[2 * i]     = __floats2half2_rn(a.x * SCALE, a.y * SCALE);
    q2[2 * i + 1] = __floats2half2_rn(a.z * SCALE, a.w * SCALE);
    k2[2 * i]     = __floats2half2_rn(b.x, b.y);
    k2[2 * i + 1] = __floats2half2_rn(b.z, b.w);
    v2[2 * i]     = __floats2half2_rn(c.x, c.y);
    v2[2 * i + 1] = __floats2half2_rn(c.z, c.w);
}

// ---------------- main fused attention (one pass, warp-private K/V) ----------------
__global__ __launch_bounds__(THREADS, 2)
void attn_main(const int* __restrict__ mask,
               float* __restrict__ out, float* __restrict__ attn)
{
    extern __shared__ char smem[];
    const uint32_t sb = su32(smem);
    const int tid = threadIdx.x;
    const int j   = tid >> 5;        // warp = key-eighth
    const int L   = tid & 31;
    const int q_  = L & 3;
    const int lrow = L & 7;
    const int lsel = L >> 3;
    const int bh  = blockIdx.y;
    const int q0  = blockIdx.x * QT;

    const __half* qg = g_q16 + ((size_t)bh * S + q0) * D;
    const __half* kg = g_k16 + (size_t)bh * S * D + (size_t)(j * 256) * D;
    const __half* vg = g_v16 + (size_t)bh * S * D + (size_t)(j * 256) * D;

    const uint32_t buf0 = sb + SM_BUF + j * 8192;
    const uint32_t buf1 = buf0 + 4096;
    float* bf      = (float*)(smem + SM_MASK);
    float* rst     = (float*)(smem + SM_RST);
    float* sInvRow = (float*)(smem + SM_INV);

    // mask -> additive bias
    {
        const int* mp = mask + (size_t)(bh >> 4) * S;
        for (int i = tid; i < S; i += THREADS) bf[i] = mp[i] ? 0.0f : -1e9f;
    }

    // Q fragments direct from global (m16n8k16 A layout), 16 rows
    uint32_t qa[4][4];
    {
        const __half* qr0 = qg + (L >> 2) * 64 + 2 * (L & 3);
        const __half* qr1 = qr0 + 8 * 64;
#pragma unroll
        for (int ks = 0; ks < 4; ks++) {
            qa[ks][0] = *(const uint32_t*)(qr0 + 16 * ks);
            qa[ks][1] = *(const uint32_t*)(qr1 + 16 * ks);
            qa[ks][2] = *(const uint32_t*)(qr0 + 16 * ks + 8);
            qa[ks][3] = *(const uint32_t*)(qr1 + 16 * ks + 8);
        }
    }

    // warp-private prologue: K chunk 0
    load_chunk(buf0, kg, L);
    CP_COMMIT();
    __syncthreads();   // mask visible (cp.async still in flight is fine)

    const uint32_t ksw1 = ((lsel ^ lrow) << 4);
    const uint32_t ksw2 = (((lsel + 4) ^ lrow) << 4);
    const int      c_base = 2 * q_;

    uint32_t P[64];                 // 16 rows x 256 keys, exp'd fp16 fragments
    float sum_lo = 0.0f, sum_hi = 0.0f;

    // ===== phase A: QK + exp2 + sums (warp-synchronous, no barriers) =====
#pragma unroll
    for (int ch = 0; ch < 8; ch++) {
        const uint32_t cbuf = (ch & 1) ? buf1 : buf0;
        const uint32_t nbuf = (ch & 1) ? buf0 : buf1;
        if (ch < 7) { load_chunk(nbuf, kg + (size_t)(ch + 1) * 32 * 64, L); CP_COMMIT(); CP_WAIT1(); }
        else        { CP_WAIT0(); }
        __syncwarp();
#pragma unroll
        for (int i = 0; i < 4; i++) {
            uint32_t kbase = cbuf + i * 1024 + lrow * 128;
            uint32_t b0, b1, b2, b3, b4, b5, b6, b7;
            LDSM4(b0, b1, b2, b3, kbase + ksw1);
            LDSM4(b4, b5, b6, b7, kbase + ksw2);
            float4 cf = make_float4(0.f, 0.f, 0.f, 0.f);
            mma_f16(cf, qa[0], b0, b1);
            mma_f16(cf, qa[1], b2, b3);
            mma_f16(cf, qa[2], b4, b5);
            mma_f16(cf, qa[3], b6, b7);
            int c0 = j * 256 + ch * 32 + i * 8 + c_base;
            float bi0 = bf[c0], bi1 = bf[c0 + 1];
            float e0 = exp2f(cf.x + bi0);
            float e1 = exp2f(cf.y + bi1);
            float e2 = exp2f(cf.z + bi0);
            float e3 = exp2f(cf.w + bi1);
            sum_lo += e0 + e1;
            sum_hi += e2 + e3;
            P[ch * 8 + (i >> 1) * 4 + (i & 1) * 2]     = packh2(e0, e1);
            P[ch * 8 + (i >> 1) * 4 + (i & 1) * 2 + 1] = packh2(e2, e3);
        }
        __syncwarp();   // all lanes done reading cbuf before it is overwritten next round
    }

    // start V chunk 0 while reducing
    load_chunk(buf0, vg, L);
    CP_COMMIT();

    // ===== phase B: row-sum reduction across quads and key-eighths =====
#pragma unroll
    for (int m = 1; m < 4; m <<= 1) {
        sum_lo += __shfl_xor_sync(0xffffffffu, sum_lo, m);
        sum_hi += __shfl_xor_sync(0xffffffffu, sum_hi, m);
    }
    const int row_lo = L >> 2;         // 0..7
    const int row_hi = row_lo + 8;
    if (q_ == 0) {
        rst[row_lo * 8 + j] = sum_lo;
        rst[row_hi * 8 + j] = sum_hi;
    }
    __syncthreads();
    float inv_lo, inv_hi;
    {
        float s0 = 0.f, s1 = 0.f;
#pragma unroll
        for (int t = 0; t < 8; t++) { s0 += rst[row_lo * 8 + t]; s1 += rst[row_hi * 8 + t]; }
        inv_lo = 1.0f / s0;
        inv_hi = 1.0f / s1;
    }
    if (j == 0 && q_ == 0) { sInvRow[row_lo] = inv_lo; sInvRow[row_hi] = inv_hi; }

    // ===== phase C: attn write from register fragments =====
    {
        float* arow_lo = attn + ((size_t)bh * S + q0 + row_lo) * S;
        float* arow_hi = attn + ((size_t)bh * S + q0 + row_hi) * S;
#pragma unroll
        for (int ch = 0; ch < 8; ch++) {
            float2 flo[4], fhi[4];
#pragma unroll
            for (int i = 0; i < 4; i++) {
                float2 t = unpackh2(P[ch * 8 + i * 2]);
                flo[i] = make_float2(t.x * inv_lo, t.y * inv_lo);
                t = unpackh2(P[ch * 8 + i * 2 + 1]);
                fhi[i] = make_float2(t.x * inv_hi, t.y * inv_hi);
            }
            quad_transpose_f2(flo, q_);
            quad_transpose_f2(fhi, q_);
            int col = j * 256 + ch * 32 + 8 * q_;
            __stcs((float4*)(arow_lo + col),
                   make_float4(flo[0].x, flo[0].y, flo[1].x, flo[1].y));
            __stcs((float4*)(arow_lo + col + 4),
                   make_float4(flo[2].x, flo[2].y, flo[3].x, flo[3].y));
            __stcs((float4*)(arow_hi + col),
                   make_float4(fhi[0].x, fhi[0].y, fhi[1].x, fhi[1].y));
            __stcs((float4*)(arow_hi + col + 4),
                   make_float4(fhi[2].x, fhi[2].y, fhi[3].x, fhi[3].y));
        }
    }

    // ===== phase D: PV over this warp's 256 keys (warp-synchronous) =====
    float4 oc[8];
#pragma unroll
    for (int nb = 0; nb < 8; nb++) oc[nb] = make_float4(0.f, 0.f, 0.f, 0.f);

#pragma unroll
    for (int ch = 0; ch < 8; ch++) {
        const uint32_t cbuf = (ch & 1) ? buf1 : buf0;
        const uint32_t nbuf = (ch & 1) ? buf0 : buf1;
        if (ch < 7) { load_chunk(nbuf, vg + (size_t)(ch + 1) * 32 * 64, L); CP_COMMIT(); CP_WAIT1(); }
        else        { CP_WAIT0(); }
        __syncwarp();
#pragma unroll
        for (int nbo = 0; nbo < 8; nbo++) {
            uint32_t vaddr = cbuf + L * 128 + ((nbo ^ lrow) << 4);
            uint32_t v0, v1, v2, v3;
            LDSM4T(v0, v1, v2, v3, vaddr);
            mma_f16(oc[nbo], &P[ch * 8],     v0, v1);
            mma_f16(oc[nbo], &P[ch * 8 + 4], v2, v3);
        }
        __syncwarp();
    }

    // ===== phase E: cross-warp O reduction via freed buffers =====
    __syncthreads();   // all warps' V reads done; buffers reusable; sInvRow visible
    {
        char* slab = smem + (size_t)j * 4096;   // 16 rows x 64 cols fp32
#pragma unroll
        for (int nb = 0; nb < 8; nb++) {
            int off = row_lo * 256 + (8 * nb + 2 * q_) * 4;
            *(float2*)(slab + off)           = make_float2(oc[nb].x, oc[nb].y);
            *(float2*)(slab + off + 8 * 256) = make_float2(oc[nb].z, oc[nb].w);
        }
    }
    __syncthreads();
    {
        int row = tid >> 4;            // 0..15
        int d0  = (tid & 15) * 4;      // 0..60
        float4 acc = make_float4(0.f, 0.f, 0.f, 0.f);
#pragma unroll
        for (int jj = 0; jj < 8; jj++) {
            float4 v = *(float4*)(smem + (size_t)jj * 4096 + row * 256 + d0 * 4);
            acc.x += v.x; acc.y += v.y; acc.z += v.z; acc.w += v.w;
        }
        float inv = sInvRow[row];
        acc.x *= inv; acc.y *= inv; acc.z *= inv; acc.w *= inv;
        *(float4*)(out + ((size_t)bh * S + q0 + row) * D + d0) = acc;
    }
}

// ---------------- launch ----------------
extern "C" void kernel_launch(void* const* d_in, const int* in_sizes, int n_in,
                              void* d_out, int out_size)
{
    const float* q    = (const float*)d_in[0];
    const float* k    = (const float*)d_in[1];
    const float* v    = (const float*)d_in[2];
    const int*   mask = (const int*)  d_in[3];

    float* out  = (float*)d_out;
    float* attn = out + (size_t)BH * S * D;

    cudaFuncSetAttribute(attn_main, cudaFuncAttributeMaxDynamicSharedMemorySize, SMEM_SZ);

    const int N4 = BH * S * D / 4;
    prep16<<<(N4 + 255) / 256, 256>>>(q, k, v);
    attn_main<<<dim3(S / QT, BH), THREADS, SMEM_SZ>>>(mask, out, attn);
}

// round 14
// speedup vs baseline: 1.5789x; 1.5789x over previous
#include <cuda_runtime.h>
#include <cuda_fp16.h>
#include <stdint.h>

// ---------------- problem constants ----------------
constexpr int B = 2, H = 16, S = 2048, D = 64;
constexpr int BH = B * H;
// fold 1/T and log2(e) into Q so exp(score) == exp2(qk)
constexpr float SCALE = 1.4426950408889634f / 32.0f;

constexpr int QT = 256;           // query rows per CTA (two 128-row halves A,B)
constexpr int NT = 128;           // keys per tile
constexpr int NTILES = S / NT;    // 16
constexpr int THREADS = 256;      // 8 warps

// smem: K/V tiles, rows of 64 fp16 padded to 72 (144B) -> conflict-free ldmatrix
constexpr int RSB = 144;
constexpr int TILE_BYTES = 128 * RSB;   // 18432

constexpr int SM_K0   = 0;
constexpr int SM_K1   = SM_K0 + TILE_BYTES;
constexpr int SM_V0   = SM_K1 + TILE_BYTES;
constexpr int SM_V1   = SM_V0 + TILE_BYTES;
constexpr int SM_MASK = SM_V1 + TILE_BYTES;      // 2048 floats (additive bias)
constexpr int SM_INV  = SM_MASK + S * 4;         // 128 floats (B-half inverses)
constexpr int SMEM_SZ = SM_INV + 512;            // 82432 B -> 2 CTAs/SM

// ---------------- device fp16 copies (K/V only) ----------------
__device__ __half g_k16[(size_t)BH * S * D];
__device__ __half g_v16[(size_t)BH * S * D];

// ---------------- helpers ----------------
__device__ __forceinline__ uint32_t su32(const void* p) {
    uint32_t a;
    asm("{ .reg .u64 t; cvta.to.shared.u64 t, %1; cvt.u32.u64 %0, t; }" : "=r"(a) : "l"(p));
    return a;
}
__device__ __forceinline__ void cpa16(uint32_t d, const void* s) {
    asm volatile("cp.async.cg.shared.global [%0], [%1], 16;" :: "r"(d), "l"(s));
}
#define CP_COMMIT() asm volatile("cp.async.commit_group;" ::: "memory")
#define CP_WAIT0()  asm volatile("cp.async.wait_group 0;" ::: "memory")
#define BARG(id)    asm volatile("bar.sync %0, 128;" :: "r"(id) : "memory")

#define LDSM4(r0, r1, r2, r3, a) \
    asm volatile("ldmatrix.sync.aligned.m8n8.x4.shared.b16 {%0,%1,%2,%3}, [%4];" \
                 : "=r"(r0), "=r"(r1), "=r"(r2), "=r"(r3) : "r"(a))
#define LDSM4T(r0, r1, r2, r3, a) \
    asm volatile("ldmatrix.sync.aligned.m8n8.x4.trans.shared.b16 {%0,%1,%2,%3}, [%4];" \
                 : "=r"(r0), "=r"(r1), "=r"(r2), "=r"(r3) : "r"(a))

__device__ __forceinline__ void mma_f16(float4& c, const uint32_t a[4],
                                        uint32_t b0, uint32_t b1) {
    asm volatile(
        "mma.sync.aligned.m16n8k16.row.col.f32.f16.f16.f32 "
        "{%0,%1,%2,%3}, {%4,%5,%6,%7}, {%8,%9}, {%0,%1,%2,%3};"
        : "+f"(c.x), "+f"(c.y), "+f"(c.z), "+f"(c.w)
        : "r"(a[0]), "r"(a[1]), "r"(a[2]), "r"(a[3]), "r"(b0), "r"(b1));
}
__device__ __forceinline__ uint32_t packh2(float a, float b) {
    __half2 h = __floats2half2_rn(a, b);
    return *(uint32_t*)&h;
}
__device__ __forceinline__ float2 shfl_xor_f2(float2 v, int m) {
    v.x = __shfl_xor_sync(0xffffffffu, v.x, m);
    v.y = __shfl_xor_sync(0xffffffffu, v.y, m);
    return v;
}
__device__ __forceinline__ void quad_transpose_f2(float2 a[4], int q) {
    {
        float2 v = (q & 1) ? a[0] : a[1];
        v = shfl_xor_f2(v, 1);
        if (q & 1) a[0] = v; else a[1] = v;
        float2 u = (q & 1) ? a[2] : a[3];
        u = shfl_xor_f2(u, 1);
        if (q & 1) a[2] = u; else a[3] = u;
    }
    {
        float2 v = (q & 2) ? a[0] : a[2];
        v = shfl_xor_f2(v, 2);
        if (q & 2) a[0] = v; else a[2] = v;
        float2 u = (q & 2) ? a[1] : a[3];
        u = shfl_xor_f2(u, 2);
        if (q & 2) a[1] = u; else a[3] = u;
    }
}

// 128-row tile -> padded smem (256 threads)
__device__ __forceinline__ void load_tile(uint32_t sdst, const __half* g, int tid) {
#pragma unroll
    for (int it = 0; it < 4; it++) {
        int f = tid + it * THREADS;
        int r = f >> 3, c = f & 7;
        cpa16(sdst + r * RSB + c * 16, g + r * 64 + c * 8);
    }
}
// 128-thread group tile load (loop3 parity)
__device__ __forceinline__ void load_tile_g(uint32_t sdst, const __half* g, int gtid) {
#pragma unroll
    for (int it = 0; it < 8; it++) {
        int f = gtid + it * 128;
        int r = f >> 3, c = f & 7;
        cpa16(sdst + r * RSB + c * 16, g + r * 64 + c * 8);
    }
}

// Q fragments for 16 rows starting at qrow0 (fp32 -> scaled fp16, m16n8k16 A layout)
__device__ __forceinline__ void load_q_frags(uint32_t qa[4][4], const float* qrow0, int L) {
    const float* p0 = qrow0 + (L >> 2) * D + 2 * (L & 3);
    const float* p1 = p0 + 8 * D;
#pragma unroll
    for (int ks = 0; ks < 4; ks++) {
        float2 v00 = *(const float2*)(p0 + 16 * ks);
        float2 v10 = *(const float2*)(p1 + 16 * ks);
        float2 v01 = *(const float2*)(p0 + 16 * ks + 8);
        float2 v11 = *(const float2*)(p1 + 16 * ks + 8);
        qa[ks][0] = packh2(v00.x * SCALE, v00.y * SCALE);
        qa[ks][1] = packh2(v10.x * SCALE, v10.y * SCALE);
        qa[ks][2] = packh2(v01.x * SCALE, v01.y * SCALE);
        qa[ks][3] = packh2(v11.x * SCALE, v11.y * SCALE);
    }
}

// ---------------- prep: fp32 -> fp16 for K and V ----------------
__global__ void prep16(const float* __restrict__ k, const float* __restrict__ v) {
    const int N4 = BH * S * D / 4;
    int i = blockIdx.x * blockDim.x + threadIdx.x;
    if (i >= N4) return;
    float4 b = ((const float4*)k)[i];
    float4 c = ((const float4*)v)[i];
    __half2* k2 = (__half2*)g_k16;
    __half2* v2 = (__half2*)g_v16;
    k2[2 * i]     = __floats2half2_rn(b.x, b.y);
    k2[2 * i + 1] = __floats2half2_rn(b.z, b.w);
    v2[2 * i]     = __floats2half2_rn(c.x, c.y);
    v2[2 * i + 1] = __floats2half2_rn(c.z, c.w);
}

// ---------------- main fused attention ----------------
__global__ __launch_bounds__(THREADS, 2)
void attn_main(const float* __restrict__ qf, const int* __restrict__ mask,
               float* __restrict__ out, float* __restrict__ attn)
{
    extern __shared__ char smem[];
    const uint32_t sb = su32(smem);
    const int tid = threadIdx.x;
    const int w   = tid >> 5;
    const int L   = tid & 31;
    const int q_  = L & 3;
    const int bh  = blockIdx.y;
    const int q0  = blockIdx.x * QT;      // A half rows q0.., B half rows q0+128..

    const float* qgA = qf + ((size_t)bh * S + q0) * D;
    const float* qgB = qgA + 128 * D;
    const __half* kg = g_k16 + (size_t)bh * S * D;
    const __half* vg = g_v16 + (size_t)bh * S * D;

    const uint32_t sK[2] = { sb + SM_K0, sb + SM_K1 };
    const uint32_t sV[2] = { sb + SM_V0, sb + SM_V1 };
    float* bf   = (float*)(smem + SM_MASK);
    float* sInv = (float*)(smem + SM_INV);

    // prologue: first K/V tile + mask bias
    load_tile(sK[0], kg, tid);
    load_tile(sV[0], vg, tid);
    CP_COMMIT();
    {
        const int* mp = mask + (size_t)(bh >> 4) * S;
        for (int i = tid; i < S; i += THREADS) bf[i] = mp[i] ? 0.0f : -1e9f;
    }

    const uint32_t ka_part = (L & 7) * RSB + (L >> 3) * 16;
    const uint32_t va_part = L * RSB;
    const int      c_base  = 2 * q_;

    // Q fragments direct from fp32 global
    uint32_t qaA[4][4], qaB[4][4];
    load_q_frags(qaA, qgA + w * 16 * D, L);
    load_q_frags(qaB, qgB + w * 16 * D, L);

    CP_WAIT0();
    __syncthreads();

    float invA_lo, invA_hi;

    // ===== loop 1: pass1(A): QK_A + exp2 + sums + PV_A =====
    {
        float4 oc[8];
#pragma unroll
        for (int nb = 0; nb < 8; nb++) oc[nb] = make_float4(0.f, 0.f, 0.f, 0.f);
        float sum_lo = 0.0f, sum_hi = 0.0f;

        for (int kt = 0; kt < NTILES; kt++) {
            const int cur = kt & 1;
            if (kt + 1 < NTILES) {
                load_tile(sK[cur ^ 1], kg + (size_t)(kt + 1) * NT * D, tid);
                load_tile(sV[cur ^ 1], vg + (size_t)(kt + 1) * NT * D, tid);
                CP_COMMIT();
            }
            const float* brow = bf + kt * NT;

#pragma unroll
            for (int kb2 = 0; kb2 < 4; kb2++) {
                uint32_t a16[2][4];
#pragma unroll
                for (int i = 0; i < 4; i++) {
                    int nb = kb2 * 4 + i;
                    uint32_t kaddr = sK[cur] + nb * 8 * RSB + ka_part;
                    uint32_t b0, b1, b2, b3, b4, b5, b6, b7;
                    LDSM4(b0, b1, b2, b3, kaddr);
                    LDSM4(b4, b5, b6, b7, kaddr + 64);
                    float4 cf = make_float4(0.f, 0.f, 0.f, 0.f);
                    mma_f16(cf, qaA[0], b0, b1);
                    mma_f16(cf, qaA[1], b2, b3);
                    mma_f16(cf, qaA[2], b4, b5);
                    mma_f16(cf, qaA[3], b6, b7);
                    int c0 = nb * 8 + c_base;
                    float bi0 = brow[c0], bi1 = brow[c0 + 1];
                    float e0 = exp2f(cf.x + bi0);
                    float e1 = exp2f(cf.y + bi1);
                    float e2 = exp2f(cf.z + bi0);
                    float e3 = exp2f(cf.w + bi1);
                    sum_lo += e0 + e1;
                    sum_hi += e2 + e3;
                    a16[i >> 1][(i & 1) * 2]     = packh2(e0, e1);
                    a16[i >> 1][(i & 1) * 2 + 1] = packh2(e2, e3);
                }
#pragma unroll
                for (int nbo = 0; nbo < 8; nbo++) {
                    uint32_t vaddr = sV[cur] + kb2 * 32 * RSB + nbo * 16 + va_part;
                    uint32_t v0, v1, v2, v3;
                    LDSM4T(v0, v1, v2, v3, vaddr);
                    mma_f16(oc[nbo], a16[0], v0, v1);
                    mma_f16(oc[nbo], a16[1], v2, v3);
                }
            }

            if (kt + 1 < NTILES) CP_WAIT0();
            __syncthreads();
        }

#pragma unroll
        for (int m = 1; m < 4; m <<= 1) {
            sum_lo += __shfl_xor_sync(0xffffffffu, sum_lo, m);
            sum_hi += __shfl_xor_sync(0xffffffffu, sum_hi, m);
        }
        invA_lo = 1.0f / sum_lo;
        invA_hi = 1.0f / sum_hi;

        float* olo = out + ((size_t)bh * S + q0 + w * 16 + (L >> 2)) * D + c_base;
        float* ohi = olo + 8 * D;
#pragma unroll
        for (int nb = 0; nb < 8; nb++) {
            *(float2*)(olo + nb * 8) = make_float2(oc[nb].x * invA_lo, oc[nb].y * invA_lo);
            *(float2*)(ohi + nb * 8) = make_float2(oc[nb].z * invA_hi, oc[nb].w * invA_hi);
        }
    }

    // ===== loop 2: fused attnA write + pass1(B); shared K LDSM =====
    float invB_lo, invB_hi;
    {
        load_tile(sK[0], kg, tid);
        load_tile(sV[0], vg, tid);
        CP_COMMIT();
        CP_WAIT0();
        __syncthreads();

        float4 oc[8];
#pragma unroll
        for (int nb = 0; nb < 8; nb++) oc[nb] = make_float4(0.f, 0.f, 0.f, 0.f);
        float sum_lo = 0.0f, sum_hi = 0.0f;

        float* arow_lo = attn + ((size_t)bh * S + q0 + w * 16 + (L >> 2)) * S;
        float* arow_hi = arow_lo + 8 * (size_t)S;

        for (int kt = 0; kt < NTILES; kt++) {
            const int cur = kt & 1;
            if (kt + 1 < NTILES) {
                load_tile(sK[cur ^ 1], kg + (size_t)(kt + 1) * NT * D, tid);
                load_tile(sV[cur ^ 1], vg + (size_t)(kt + 1) * NT * D, tid);
                CP_COMMIT();
            }
            const float* brow = bf + kt * NT;

#pragma unroll
            for (int kb2 = 0; kb2 < 4; kb2++) {
                float4 cfA[4];
                uint32_t a16[2][4];
#pragma unroll
                for (int i = 0; i < 4; i++) {
                    int nb = kb2 * 4 + i;
                    uint32_t kaddr = sK[cur] + nb * 8 * RSB + ka_part;
                    uint32_t b0, b1, b2, b3, b4, b5, b6, b7;
                    LDSM4(b0, b1, b2, b3, kaddr);
                    LDSM4(b4, b5, b6, b7, kaddr + 64);
                    cfA[i] = make_float4(0.f, 0.f, 0.f, 0.f);
                    mma_f16(cfA[i], qaA[0], b0, b1);
                    mma_f16(cfA[i], qaA[1], b2, b3);
                    mma_f16(cfA[i], qaA[2], b4, b5);
                    mma_f16(cfA[i], qaA[3], b6, b7);
                    float4 cfB = make_float4(0.f, 0.f, 0.f, 0.f);
                    mma_f16(cfB, qaB[0], b0, b1);
                    mma_f16(cfB, qaB[1], b2, b3);
                    mma_f16(cfB, qaB[2], b4, b5);
                    mma_f16(cfB, qaB[3], b6, b7);
                    int c0 = nb * 8 + c_base;
                    float bi0 = brow[c0], bi1 = brow[c0 + 1];
                    float e0 = exp2f(cfB.x + bi0);
                    float e1 = exp2f(cfB.y + bi1);
                    float e2 = exp2f(cfB.z + bi0);
                    float e3 = exp2f(cfB.w + bi1);
                    sum_lo += e0 + e1;
                    sum_hi += e2 + e3;
                    a16[i >> 1][(i & 1) * 2]     = packh2(e0, e1);
                    a16[i >> 1][(i & 1) * 2 + 1] = packh2(e2, e3);
                }
                // attn_A write for these 32 keys
                {
                    float2 flo[4], fhi[4];
#pragma unroll
                    for (int i = 0; i < 4; i++) {
                        int c0 = (kb2 * 4 + i) * 8 + c_base;
                        float bi0 = brow[c0], bi1 = brow[c0 + 1];
                        flo[i] = make_float2(exp2f(cfA[i].x + bi0) * invA_lo,
                                             exp2f(cfA[i].y + bi1) * invA_lo);
                        fhi[i] = make_float2(exp2f(cfA[i].z + bi0) * invA_hi,
                                             exp2f(cfA[i].w + bi1) * invA_hi);
                    }
                    quad_transpose_f2(flo, q_);
                    quad_transpose_f2(fhi, q_);
                    int col = kt * NT + kb2 * 32 + 8 * q_;
                    __stcs((float4*)(arow_lo + col),
                           make_float4(flo[0].x, flo[0].y, flo[1].x, flo[1].y));
                    __stcs((float4*)(arow_lo + col + 4),
                           make_float4(flo[2].x, flo[2].y, flo[3].x, flo[3].y));
                    __stcs((float4*)(arow_hi + col),
                           make_float4(fhi[0].x, fhi[0].y, fhi[1].x, fhi[1].y));
                    __stcs((float4*)(arow_hi + col + 4),
                           make_float4(fhi[2].x, fhi[2].y, fhi[3].x, fhi[3].y));
                }
                // PV for B
#pragma unroll
                for (int nbo = 0; nbo < 8; nbo++) {
                    uint32_t vaddr = sV[cur] + kb2 * 32 * RSB + nbo * 16 + va_part;
                    uint32_t v0, v1, v2, v3;
                    LDSM4T(v0, v1, v2, v3, vaddr);
                    mma_f16(oc[nbo], a16[0], v0, v1);
                    mma_f16(oc[nbo], a16[1], v2, v3);
                }
            }

            if (kt + 1 < NTILES) CP_WAIT0();
            __syncthreads();
        }

#pragma unroll
        for (int m = 1; m < 4; m <<= 1) {
            sum_lo += __shfl_xor_sync(0xffffffffu, sum_lo, m);
            sum_hi += __shfl_xor_sync(0xffffffffu, sum_hi, m);
        }
        invB_lo = 1.0f / sum_lo;
        invB_hi = 1.0f / sum_hi;

        if (q_ == 0) {
            sInv[w * 16 + (L >> 2)]     = invB_lo;
            sInv[w * 16 + 8 + (L >> 2)] = invB_hi;
        }

        float* olo = out + ((size_t)bh * S + q0 + 128 + w * 16 + (L >> 2)) * D + c_base;
        float* ohi = olo + 8 * D;
#pragma unroll
        for (int nb = 0; nb < 8; nb++) {
            *(float2*)(olo + nb * 8) = make_float2(oc[nb].x * invB_lo, oc[nb].y * invB_lo);
            *(float2*)(ohi + nb * 8) = make_float2(oc[nb].z * invB_hi, oc[nb].w * invB_hi);
        }
    }
    __syncthreads();   // sInv visible; all buffers free

    // ===== loop 3: attn_B write (tile-parity split groups, 32 rows/warp) =====
    {
        const int p    = w >> 2;
        const int g    = w & 3;
        const int gtid = tid & 127;
        const int bar  = 1 + p;
        const uint32_t bufs[2] = { p ? sV[0] : sK[0], p ? sV[1] : sK[1] };

        uint32_t qa2[2][4][4];
        load_q_frags(qa2[0], qgB + (g * 32) * D, L);
        load_q_frags(qa2[1], qgB + (g * 32 + 16) * D, L);

        float invA2[2], invB2[2];
#pragma unroll
        for (int mb = 0; mb < 2; mb++) {
            invA2[mb] = sInv[g * 32 + mb * 16 + (L >> 2)];
            invB2[mb] = sInv[g * 32 + mb * 16 + 8 + (L >> 2)];
        }
        float* arow0[2];
#pragma unroll
        for (int mb = 0; mb < 2; mb++)
            arow0[mb] = attn + ((size_t)bh * S + q0 + 128 + g * 32 + mb * 16 + (L >> 2)) * S;

        load_tile_g(bufs[0], kg + (size_t)p * NT * D, gtid);
        CP_COMMIT();
        CP_WAIT0();
        BARG(bar);

        for (int i = 0; i < 8; i++) {
            const int kt  = p + 2 * i;
            const int cur = i & 1;
            if (i + 1 < 8) {
                load_tile_g(bufs[cur ^ 1], kg + (size_t)(kt + 2) * NT * D, gtid);
                CP_COMMIT();
            }
            const float* brow = bf + kt * NT;

#pragma unroll
            for (int kb2 = 0; kb2 < 4; kb2++) {
                float4 cf[2][4];
#pragma unroll
                for (int i4 = 0; i4 < 4; i4++) {
                    int nb = kb2 * 4 + i4;
                    uint32_t kaddr = bufs[cur] + nb * 8 * RSB + ka_part;
                    uint32_t b0, b1, b2, b3, b4, b5, b6, b7;
                    LDSM4(b0, b1, b2, b3, kaddr);
                    LDSM4(b4, b5, b6, b7, kaddr + 64);
#pragma unroll
                    for (int mb = 0; mb < 2; mb++) {
                        cf[mb][i4] = make_float4(0.f, 0.f, 0.f, 0.f);
                        mma_f16(cf[mb][i4], qa2[mb][0], b0, b1);
                        mma_f16(cf[mb][i4], qa2[mb][1], b2, b3);
                        mma_f16(cf[mb][i4], qa2[mb][2], b4, b5);
                        mma_f16(cf[mb][i4], qa2[mb][3], b6, b7);
                    }
                }
#pragma unroll
                for (int mb = 0; mb < 2; mb++) {
                    float2 flo[4], fhi[4];
#pragma unroll
                    for (int i4 = 0; i4 < 4; i4++) {
                        int c0 = (kb2 * 4 + i4) * 8 + c_base;
                        float bi0 = brow[c0], bi1 = brow[c0 + 1];
                        flo[i4] = make_float2(exp2f(cf[mb][i4].x + bi0) * invA2[mb],
                                              exp2f(cf[mb][i4].y + bi1) * invA2[mb]);
                        fhi[i4] = make_float2(exp2f(cf[mb][i4].z + bi0) * invB2[mb],
                                              exp2f(cf[mb][i4].w + bi1) * invB2[mb]);
                    }
                    quad_transpose_f2(flo, q_);
                    quad_transpose_f2(fhi, q_);
                    int col = kt * NT + kb2 * 32 + 8 * q_;
                    float* alo = arow0[mb];
                    float* ahi = alo + 8 * (size_t)S;
                    __stcs((float4*)(alo + col),
                           make_float4(flo[0].x, flo[0].y, flo[1].x, flo[1].y));
                    __stcs((float4*)(alo + col + 4),
                           make_float4(flo[2].x, flo[2].y, flo[3].x, flo[3].y));
                    __stcs((float4*)(ahi + col),
                           make_float4(fhi[0].x, fhi[0].y, fhi[1].x, fhi[1].y));
                    __stcs((float4*)(ahi + col + 4),
                           make_float4(fhi[2].x, fhi[2].y, fhi[3].x, fhi[3].y));
                }
            }

            if (i + 1 < 8) CP_WAIT0();
            BARG(bar);
        }
    }
}

// ---------------- launch ----------------
extern "C" void kernel_launch(void* const* d_in, const int* in_sizes, int n_in,
                              void* d_out, int out_size)
{
    const float* q    = (const float*)d_in[0];
    const float* k    = (const float*)d_in[1];
    const float* v    = (const float*)d_in[2];
    const int*   mask = (const int*)  d_in[3];

    float* out  = (float*)d_out;
    float* attn = out + (size_t)BH * S * D;

    cudaFuncSetAttribute(attn_main, cudaFuncAttributeMaxDynamicSharedMemorySize, SMEM_SZ);

    const int N4 = BH * S * D / 4;
    prep16<<<(N4 + 255) / 256, 256>>>(k, v);
    attn_main<<<dim3(S / QT, BH), THREADS, SMEM_SZ>>>(q, mask, out, attn);
}

// round 15
// speedup vs baseline: 1.5884x; 1.0061x over previous
#include <cuda_runtime.h>
#include <cuda_fp16.h>
#include <stdint.h>

// ---------------- problem constants ----------------
constexpr int B = 2, H = 16, S = 2048, D = 64;
constexpr int BH = B * H;
// fold 1/T and log2(e) into Q so exp(score) == exp2(qk)
constexpr float SCALE = 1.4426950408889634f / 32.0f;

constexpr int QT = 256;           // query rows per CTA (two 128-row halves A,B)
constexpr int NT = 128;           // keys per tile
constexpr int NTILES = S / NT;    // 16
constexpr int THREADS = 256;      // 8 warps; warp w owns rows 16w..16w+15 of each half

// smem: K/V tiles, rows of 64 fp16 padded to 72 (144B) -> conflict-free ldmatrix
constexpr int RSB = 144;
constexpr int TILE_BYTES = 128 * RSB;   // 18432

constexpr int SM_K0   = 0;
constexpr int SM_K1   = SM_K0 + TILE_BYTES;
constexpr int SM_V0   = SM_K1 + TILE_BYTES;
constexpr int SM_V1   = SM_V0 + TILE_BYTES;
constexpr int SM_MASK = SM_V1 + TILE_BYTES;      // 2048 floats (additive bias)
constexpr int SMEM_SZ = SM_MASK + S * 4;         // 81920 B -> 2 CTAs/SM

// ---------------- device fp16 copies (K/V only) ----------------
__device__ __half g_k16[(size_t)BH * S * D];
__device__ __half g_v16[(size_t)BH * S * D];

// ---------------- helpers ----------------
__device__ __forceinline__ uint32_t su32(const void* p) {
    uint32_t a;
    asm("{ .reg .u64 t; cvta.to.shared.u64 t, %1; cvt.u32.u64 %0, t; }" : "=r"(a) : "l"(p));
    return a;
}
__device__ __forceinline__ void cpa16(uint32_t d, const void* s) {
    asm volatile("cp.async.cg.shared.global [%0], [%1], 16;" :: "r"(d), "l"(s));
}
#define CP_COMMIT() asm volatile("cp.async.commit_group;" ::: "memory")
#define CP_WAIT0()  asm volatile("cp.async.wait_group 0;" ::: "memory")

#define LDSM4(r0, r1, r2, r3, a) \
    asm volatile("ldmatrix.sync.aligned.m8n8.x4.shared.b16 {%0,%1,%2,%3}, [%4];" \
                 : "=r"(r0), "=r"(r1), "=r"(r2), "=r"(r3) : "r"(a))
#define LDSM4T(r0, r1, r2, r3, a) \
    asm volatile("ldmatrix.sync.aligned.m8n8.x4.trans.shared.b16 {%0,%1,%2,%3}, [%4];" \
                 : "=r"(r0), "=r"(r1), "=r"(r2), "=r"(r3) : "r"(a))

__device__ __forceinline__ void mma_f16(float4& c, const uint32_t a[4],
                                        uint32_t b0, uint32_t b1) {
    asm volatile(
        "mma.sync.aligned.m16n8k16.row.col.f32.f16.f16.f32 "
        "{%0,%1,%2,%3}, {%4,%5,%6,%7}, {%8,%9}, {%0,%1,%2,%3};"
        : "+f"(c.x), "+f"(c.y), "+f"(c.z), "+f"(c.w)
        : "r"(a[0]), "r"(a[1]), "r"(a[2]), "r"(a[3]), "r"(b0), "r"(b1));
}
__device__ __forceinline__ uint32_t packh2(float a, float b) {
    __half2 h = __floats2half2_rn(a, b);
    return *(uint32_t*)&h;
}
__device__ __forceinline__ float2 unpackh2(uint32_t u) {
    return __half22float2(*(__half2*)&u);
}
__device__ __forceinline__ float2 shfl_xor_f2(float2 v, int m) {
    v.x = __shfl_xor_sync(0xffffffffu, v.x, m);
    v.y = __shfl_xor_sync(0xffffffffu, v.y, m);
    return v;
}
__device__ __forceinline__ void quad_transpose_f2(float2 a[4], int q) {
    {
        float2 v = (q & 1) ? a[0] : a[1];
        v = shfl_xor_f2(v, 1);
        if (q & 1) a[0] = v; else a[1] = v;
        float2 u = (q & 1) ? a[2] : a[3];
        u = shfl_xor_f2(u, 1);
        if (q & 1) a[2] = u; else a[3] = u;
    }
    {
        float2 v = (q & 2) ? a[0] : a[2];
        v = shfl_xor_f2(v, 2);
        if (q & 2) a[0] = v; else a[2] = v;
        float2 u = (q & 2) ? a[1] : a[3];
        u = shfl_xor_f2(u, 2);
        if (q & 2) a[1] = u; else a[3] = u;
    }
}

// 128-row tile -> padded smem (256 threads)
__device__ __forceinline__ void load_tile(uint32_t sdst, const __half* g, int tid) {
#pragma unroll
    for (int it = 0; it < 4; it++) {
        int f = tid + it * THREADS;
        int r = f >> 3, c = f & 7;
        cpa16(sdst + r * RSB + c * 16, g + r * 64 + c * 8);
    }
}

// Q fragments for 16 rows starting at qrow0 (fp32 -> scaled fp16, m16n8k16 A layout)
__device__ __forceinline__ void load_q_frags(uint32_t qa[4][4], const float* qrow0, int L) {
    const float* p0 = qrow0 + (L >> 2) * D + 2 * (L & 3);
    const float* p1 = p0 + 8 * D;
#pragma unroll
    for (int ks = 0; ks < 4; ks++) {
        float2 v00 = *(const float2*)(p0 + 16 * ks);
        float2 v10 = *(const float2*)(p1 + 16 * ks);
        float2 v01 = *(const float2*)(p0 + 16 * ks + 8);
        float2 v11 = *(const float2*)(p1 + 16 * ks + 8);
        qa[ks][0] = packh2(v00.x * SCALE, v00.y * SCALE);
        qa[ks][1] = packh2(v10.x * SCALE, v10.y * SCALE);
        qa[ks][2] = packh2(v01.x * SCALE, v01.y * SCALE);
        qa[ks][3] = packh2(v11.x * SCALE, v11.y * SCALE);
    }
}

// ---------------- prep: fp32 -> fp16 for K and V ----------------
__global__ void prep16(const float* __restrict__ k, const float* __restrict__ v) {
    const int N4 = BH * S * D / 4;
    int i = blockIdx.x * blockDim.x + threadIdx.x;
    if (i >= N4) return;
    float4 b = ((const float4*)k)[i];
    float4 c = ((const float4*)v)[i];
    __half2* k2 = (__half2*)g_k16;
    __half2* v2 = (__half2*)g_v16;
    k2[2 * i]     = __floats2half2_rn(b.x, b.y);
    k2[2 * i + 1] = __floats2half2_rn(b.z, b.w);
    v2[2 * i]     = __floats2half2_rn(c.x, c.y);
    v2[2 * i + 1] = __floats2half2_rn(c.z, c.w);
}

// ---------------- main fused attention (2-loop structure) ----------------
__global__ __launch_bounds__(THREADS, 2)
void attn_main(const float* __restrict__ qf, const int* __restrict__ mask,
               float* __restrict__ out, float* __restrict__ attn)
{
    extern __shared__ char smem[];
    const uint32_t sb = su32(smem);
    const int tid = threadIdx.x;
    const int w   = tid >> 5;
    const int L   = tid & 31;
    const int q_  = L & 3;
    const int bh  = blockIdx.y;
    const int q0  = blockIdx.x * QT;      // A: rows q0.., B: rows q0+128..

    const float* qgA = qf + ((size_t)bh * S + q0) * D;
    const float* qgB = qgA + 128 * D;
    const __half* kg = g_k16 + (size_t)bh * S * D;
    const __half* vg = g_v16 + (size_t)bh * S * D;

    const uint32_t sK[2] = { sb + SM_K0, sb + SM_K1 };
    const uint32_t sV[2] = { sb + SM_V0, sb + SM_V1 };
    float* bf = (float*)(smem + SM_MASK);

    // prologue: first K/V tile + mask bias
    load_tile(sK[0], kg, tid);
    load_tile(sV[0], vg, tid);
    CP_COMMIT();
    {
        const int* mp = mask + (size_t)(bh >> 4) * S;
        for (int i = tid; i < S; i += THREADS) bf[i] = mp[i] ? 0.0f : -1e9f;
    }

    const uint32_t ka_part = (L & 7) * RSB + (L >> 3) * 16;
    const uint32_t va_part = L * RSB;
    const int      c_base  = 2 * q_;

    // Q fragments for both halves, direct from fp32 global
    uint32_t qaA[4][4], qaB[4][4];
    load_q_frags(qaA, qgA + w * 16 * D, L);
    load_q_frags(qaB, qgB + w * 16 * D, L);

    CP_WAIT0();
    __syncthreads();

    float invA_lo, invA_hi, invB_lo, invB_hi;

    // ===== loop 1: QK_A + QK_B (shared LDSM) -> sums(A,B) + PV_A =====
    {
        float4 oc[8];
#pragma unroll
        for (int nb = 0; nb < 8; nb++) oc[nb] = make_float4(0.f, 0.f, 0.f, 0.f);
        float sA_lo = 0.0f, sA_hi = 0.0f, sB_lo = 0.0f, sB_hi = 0.0f;

        for (int kt = 0; kt < NTILES; kt++) {
            const int cur = kt & 1;
            if (kt + 1 < NTILES) {
                load_tile(sK[cur ^ 1], kg + (size_t)(kt + 1) * NT * D, tid);
                load_tile(sV[cur ^ 1], vg + (size_t)(kt + 1) * NT * D, tid);
                CP_COMMIT();
            }
            const float* brow = bf + kt * NT;

#pragma unroll
            for (int kb2 = 0; kb2 < 4; kb2++) {
                uint32_t a16[2][4];
#pragma unroll
                for (int i = 0; i < 4; i++) {
                    int nb = kb2 * 4 + i;
                    uint32_t kaddr = sK[cur] + nb * 8 * RSB + ka_part;
                    uint32_t b0, b1, b2, b3, b4, b5, b6, b7;
                    LDSM4(b0, b1, b2, b3, kaddr);
                    LDSM4(b4, b5, b6, b7, kaddr + 64);
                    int c0 = nb * 8 + c_base;
                    float bi0 = brow[c0], bi1 = brow[c0 + 1];
                    // A half -> sum + fragments for PV_A
                    {
                        float4 cf = make_float4(0.f, 0.f, 0.f, 0.f);
                        mma_f16(cf, qaA[0], b0, b1);
                        mma_f16(cf, qaA[1], b2, b3);
                        mma_f16(cf, qaA[2], b4, b5);
                        mma_f16(cf, qaA[3], b6, b7);
                        float e0 = exp2f(cf.x + bi0);
                        float e1 = exp2f(cf.y + bi1);
                        float e2 = exp2f(cf.z + bi0);
                        float e3 = exp2f(cf.w + bi1);
                        sA_lo += e0 + e1;
                        sA_hi += e2 + e3;
                        a16[i >> 1][(i & 1) * 2]     = packh2(e0, e1);
                        a16[i >> 1][(i & 1) * 2 + 1] = packh2(e2, e3);
                    }
                    // B half -> sum only
                    {
                        float4 cf = make_float4(0.f, 0.f, 0.f, 0.f);
                        mma_f16(cf, qaB[0], b0, b1);
                        mma_f16(cf, qaB[1], b2, b3);
                        mma_f16(cf, qaB[2], b4, b5);
                        mma_f16(cf, qaB[3], b6, b7);
                        sB_lo += exp2f(cf.x + bi0) + exp2f(cf.y + bi1);
                        sB_hi += exp2f(cf.z + bi0) + exp2f(cf.w + bi1);
                    }
                }
#pragma unroll
                for (int nbo = 0; nbo < 8; nbo++) {
                    uint32_t vaddr = sV[cur] + kb2 * 32 * RSB + nbo * 16 + va_part;
                    uint32_t v0, v1, v2, v3;
                    LDSM4T(v0, v1, v2, v3, vaddr);
                    mma_f16(oc[nbo], a16[0], v0, v1);
                    mma_f16(oc[nbo], a16[1], v2, v3);
                }
            }

            if (kt + 1 < NTILES) CP_WAIT0();
            __syncthreads();
        }

#pragma unroll
        for (int m = 1; m < 4; m <<= 1) {
            sA_lo += __shfl_xor_sync(0xffffffffu, sA_lo, m);
            sA_hi += __shfl_xor_sync(0xffffffffu, sA_hi, m);
            sB_lo += __shfl_xor_sync(0xffffffffu, sB_lo, m);
            sB_hi += __shfl_xor_sync(0xffffffffu, sB_hi, m);
        }
        invA_lo = 1.0f / sA_lo;
        invA_hi = 1.0f / sA_hi;
        invB_lo = 1.0f / sB_lo;
        invB_hi = 1.0f / sB_hi;

        // O_A write
        float* olo = out + ((size_t)bh * S + q0 + w * 16 + (L >> 2)) * D + c_base;
        float* ohi = olo + 8 * D;
#pragma unroll
        for (int nb = 0; nb < 8; nb++) {
            *(float2*)(olo + nb * 8) = make_float2(oc[nb].x * invA_lo, oc[nb].y * invA_lo);
            *(float2*)(ohi + nb * 8) = make_float2(oc[nb].z * invA_hi, oc[nb].w * invA_hi);
        }
    }

    // ===== loop 2: attn_A + attn_B writes + PV_B (shared K LDSM) =====
    {
        load_tile(sK[0], kg, tid);
        load_tile(sV[0], vg, tid);
        CP_COMMIT();
        CP_WAIT0();
        __syncthreads();

        float4 oc[8];
#pragma unroll
        for (int nb = 0; nb < 8; nb++) oc[nb] = make_float4(0.f, 0.f, 0.f, 0.f);

        float* aAlo = attn + ((size_t)bh * S + q0 + w * 16 + (L >> 2)) * S;
        float* aAhi = aAlo + 8 * (size_t)S;
        float* aBlo = attn + ((size_t)bh * S + q0 + 128 + w * 16 + (L >> 2)) * S;
        float* aBhi = aBlo + 8 * (size_t)S;

        for (int kt = 0; kt < NTILES; kt++) {
            const int cur = kt & 1;
            if (kt + 1 < NTILES) {
                load_tile(sK[cur ^ 1], kg + (size_t)(kt + 1) * NT * D, tid);
                load_tile(sV[cur ^ 1], vg + (size_t)(kt + 1) * NT * D, tid);
                CP_COMMIT();
            }
            const float* brow = bf + kt * NT;

#pragma unroll
            for (int kb2 = 0; kb2 < 4; kb2++) {
                float4 cfA[4];
                uint32_t a16[2][4];
#pragma unroll
                for (int i = 0; i < 4; i++) {
                    int nb = kb2 * 4 + i;
                    uint32_t kaddr = sK[cur] + nb * 8 * RSB + ka_part;
                    uint32_t b0, b1, b2, b3, b4, b5, b6, b7;
                    LDSM4(b0, b1, b2, b3, kaddr);
                    LDSM4(b4, b5, b6, b7, kaddr + 64);
                    cfA[i] = make_float4(0.f, 0.f, 0.f, 0.f);
                    mma_f16(cfA[i], qaA[0], b0, b1);
                    mma_f16(cfA[i], qaA[1], b2, b3);
                    mma_f16(cfA[i], qaA[2], b4, b5);
                    mma_f16(cfA[i], qaA[3], b6, b7);
                    float4 cfB = make_float4(0.f, 0.f, 0.f, 0.f);
                    mma_f16(cfB, qaB[0], b0, b1);
                    mma_f16(cfB, qaB[1], b2, b3);
                    mma_f16(cfB, qaB[2], b4, b5);
                    mma_f16(cfB, qaB[3], b6, b7);
                    int c0 = nb * 8 + c_base;
                    float bi0 = brow[c0], bi1 = brow[c0 + 1];
                    float e0 = exp2f(cfB.x + bi0);
                    float e1 = exp2f(cfB.y + bi1);
                    float e2 = exp2f(cfB.z + bi0);
                    float e3 = exp2f(cfB.w + bi1);
                    a16[i >> 1][(i & 1) * 2]     = packh2(e0, e1);
                    a16[i >> 1][(i & 1) * 2 + 1] = packh2(e2, e3);
                }
                const int col = kt * NT + kb2 * 32 + 8 * q_;
                // attn_A write (exp of cfA)
                {
                    float2 flo[4], fhi[4];
#pragma unroll
                    for (int i = 0; i < 4; i++) {
                        int c0 = (kb2 * 4 + i) * 8 + c_base;
                        float bi0 = brow[c0], bi1 = brow[c0 + 1];
                        flo[i] = make_float2(exp2f(cfA[i].x + bi0) * invA_lo,
                                             exp2f(cfA[i].y + bi1) * invA_lo);
                        fhi[i] = make_float2(exp2f(cfA[i].z + bi0) * invA_hi,
                                             exp2f(cfA[i].w + bi1) * invA_hi);
                    }
                    quad_transpose_f2(flo, q_);
                    quad_transpose_f2(fhi, q_);
                    __stcs((float4*)(aAlo + col),
                           make_float4(flo[0].x, flo[0].y, flo[1].x, flo[1].y));
                    __stcs((float4*)(aAlo + col + 4),
                           make_float4(flo[2].x, flo[2].y, flo[3].x, flo[3].y));
                    __stcs((float4*)(aAhi + col),
                           make_float4(fhi[0].x, fhi[0].y, fhi[1].x, fhi[1].y));
                    __stcs((float4*)(aAhi + col + 4),
                           make_float4(fhi[2].x, fhi[2].y, fhi[3].x, fhi[3].y));
                }
                // attn_B write (reuse a16 fragments)
                {
                    float2 flo[4], fhi[4];
#pragma unroll
                    for (int i = 0; i < 4; i++) {
                        float2 t = unpackh2(a16[i >> 1][(i & 1) * 2]);
                        flo[i] = make_float2(t.x * invB_lo, t.y * invB_lo);
                        t = unpackh2(a16[i >> 1][(i & 1) * 2 + 1]);
                        fhi[i] = make_float2(t.x * invB_hi, t.y * invB_hi);
                    }
                    quad_transpose_f2(flo, q_);
                    quad_transpose_f2(fhi, q_);
                    __stcs((float4*)(aBlo + col),
                           make_float4(flo[0].x, flo[0].y, flo[1].x, flo[1].y));
                    __stcs((float4*)(aBlo + col + 4),
                           make_float4(flo[2].x, flo[2].y, flo[3].x, flo[3].y));
                    __stcs((float4*)(aBhi + col),
                           make_float4(fhi[0].x, fhi[0].y, fhi[1].x, fhi[1].y));
                    __stcs((float4*)(aBhi + col + 4),
                           make_float4(fhi[2].x, fhi[2].y, fhi[3].x, fhi[3].y));
                }
                // PV_B (reuse a16 fragments)
#pragma unroll
                for (int nbo = 0; nbo < 8; nbo++) {
                    uint32_t vaddr = sV[cur] + kb2 * 32 * RSB + nbo * 16 + va_part;
                    uint32_t v0, v1, v2, v3;
                    LDSM4T(v0, v1, v2, v3, vaddr);
                    mma_f16(oc[nbo], a16[0], v0, v1);
                    mma_f16(oc[nbo], a16[1], v2, v3);
                }
            }

            if (kt + 1 < NTILES) CP_WAIT0();
            __syncthreads();
        }

        // O_B write
        float* olo = out + ((size_t)bh * S + q0 + 128 + w * 16 + (L >> 2)) * D + c_base;
        float* ohi = olo + 8 * D;
#pragma unroll
        for (int nb = 0; nb < 8; nb++) {
            *(float2*)(olo + nb * 8) = make_float2(oc[nb].x * invB_lo, oc[nb].y * invB_lo);
            *(float2*)(ohi + nb * 8) = make_float2(oc[nb].z * invB_hi, oc[nb].w * invB_hi);
        }
    }
}

// ---------------- launch ----------------
extern "C" void kernel_launch(void* const* d_in, const int* in_sizes, int n_in,
                              void* d_out, int out_size)
{
    const float* q    = (const float*)d_in[0];
    const float* k    = (const float*)d_in[1];
    const float* v    = (const float*)d_in[2];
    const int*   mask = (const int*)  d_in[3];

    float* out  = (float*)d_out;
    float* attn = out + (size_t)BH * S * D;

    cudaFuncSetAttribute(attn_main, cudaFuncAttributeMaxDynamicSharedMemorySize, SMEM_SZ);

    const int N4 = BH * S * D / 4;
    prep16<<<(N4 + 255) / 256, 256>>>(k, v);
    attn_main<<<dim3(S / QT, BH), THREADS, SMEM_SZ>>>(q, mask, out, attn);
}

// round 16
// speedup vs baseline: 1.6458x; 1.0361x over previous
#include <cuda_runtime.h>
#include <cuda_fp16.h>
#include <stdint.h>

// ---------------- problem constants ----------------
constexpr int B = 2, H = 16, S = 2048, D = 64;
constexpr int BH = B * H;
// fold 1/T and log2(e) into Q so exp(score) == exp2(qk)
constexpr float SCALE = 1.4426950408889634f / 32.0f;

constexpr int QT = 256;           // query rows per CTA (two 128-row halves A,B)
constexpr int NT = 128;           // keys per tile
constexpr int NTILES = S / NT;    // 16
constexpr int THREADS = 256;      // 8 warps; warp w owns rows 16w..16w+15 of each half

// smem: K/V tiles, rows of 64 fp16 padded to 72 (144B) -> conflict-free ldmatrix
constexpr int RSB = 144;
constexpr int TILE_BYTES = 128 * RSB;   // 18432

constexpr int SM_K0   = 0;
constexpr int SM_K1   = SM_K0 + TILE_BYTES;
constexpr int SM_V0   = SM_K1 + TILE_BYTES;
constexpr int SM_V1   = SM_V0 + TILE_BYTES;
constexpr int SM_BIAS = SM_V1 + TILE_BYTES;      // 1024 half2 (4KB)
constexpr int SMEM_SZ = SM_BIAS + (S / 2) * 4;   // 77824 B -> 2 CTAs/SM

constexpr uint32_t ONES2 = 0x3C003C00u;          // half2(1,1)

// ---------------- device fp16 copies (K/V only) ----------------
__device__ __half g_k16[(size_t)BH * S * D];
__device__ __half g_v16[(size_t)BH * S * D];

// ---------------- helpers ----------------
__device__ __forceinline__ uint32_t su32(const void* p) {
    uint32_t a;
    asm("{ .reg .u64 t; cvta.to.shared.u64 t, %1; cvt.u32.u64 %0, t; }" : "=r"(a) : "l"(p));
    return a;
}
__device__ __forceinline__ void cpa16(uint32_t d, const void* s) {
    asm volatile("cp.async.cg.shared.global [%0], [%1], 16;" :: "r"(d), "l"(s));
}
#define CP_COMMIT() asm volatile("cp.async.commit_group;" ::: "memory")
#define CP_WAIT0()  asm volatile("cp.async.wait_group 0;" ::: "memory")

#define LDSM4(r0, r1, r2, r3, a) \
    asm volatile("ldmatrix.sync.aligned.m8n8.x4.shared.b16 {%0,%1,%2,%3}, [%4];" \
                 : "=r"(r0), "=r"(r1), "=r"(r2), "=r"(r3) : "r"(a))
#define LDSM4T(r0, r1, r2, r3, a) \
    asm volatile("ldmatrix.sync.aligned.m8n8.x4.trans.shared.b16 {%0,%1,%2,%3}, [%4];" \
                 : "=r"(r0), "=r"(r1), "=r"(r2), "=r"(r3) : "r"(a))

__device__ __forceinline__ void mma_f16(float4& c, const uint32_t a[4],
                                        uint32_t b0, uint32_t b1) {
    asm volatile(
        "mma.sync.aligned.m16n8k16.row.col.f32.f16.f16.f32 "
        "{%0,%1,%2,%3}, {%4,%5,%6,%7}, {%8,%9}, {%0,%1,%2,%3};"
        : "+f"(c.x), "+f"(c.y), "+f"(c.z), "+f"(c.w)
        : "r"(a[0]), "r"(a[1]), "r"(a[2]), "r"(a[3]), "r"(b0), "r"(b1));
}
__device__ __forceinline__ uint32_t packh2(float a, float b) {
    __half2 h = __floats2half2_rn(a, b);
    return *(uint32_t*)&h;
}
__device__ __forceinline__ float2 unpackh2(uint32_t u) {
    return __half22float2(*(__half2*)&u);
}
// exp2 of a score pair with additive half2 bias; returns packed fp16x2
__device__ __forceinline__ uint32_t exp2pair(float a, float b, __half2 bias2) {
    __half2 h = __floats2half2_rn(a, b);
    h = h2exp2(__hadd2(h, bias2));
    return *(uint32_t*)&h;
}
__device__ __forceinline__ float2 shfl_xor_f2(float2 v, int m) {
    v.x = __shfl_xor_sync(0xffffffffu, v.x, m);
    v.y = __shfl_xor_sync(0xffffffffu, v.y, m);
    return v;
}
__device__ __forceinline__ void quad_transpose_f2(float2 a[4], int q) {
    {
        float2 v = (q & 1) ? a[0] : a[1];
        v = shfl_xor_f2(v, 1);
        if (q & 1) a[0] = v; else a[1] = v;
        float2 u = (q & 1) ? a[2] : a[3];
        u = shfl_xor_f2(u, 1);
        if (q & 1) a[2] = u; else a[3] = u;
    }
    {
        float2 v = (q & 2) ? a[0] : a[2];
        v = shfl_xor_f2(v, 2);
        if (q & 2) a[0] = v; else a[2] = v;
        float2 u = (q & 2) ? a[1] : a[3];
        u = shfl_xor_f2(u, 2);
        if (q & 2) a[1] = u; else a[3] = u;
    }
}

// 128-row tile -> padded smem (256 threads)
__device__ __forceinline__ void load_tile(uint32_t sdst, const __half* g, int tid) {
#pragma unroll
    for (int it = 0; it < 4; it++) {
        int f = tid + it * THREADS;
        int r = f >> 3, c = f & 7;
        cpa16(sdst + r * RSB + c * 16, g + r * 64 + c * 8);
    }
}

// Q fragments for 16 rows starting at qrow0 (fp32 -> scaled fp16, m16n8k16 A layout)
__device__ __forceinline__ void load_q_frags(uint32_t qa[4][4], const float* qrow0, int L) {
    const float* p0 = qrow0 + (L >> 2) * D + 2 * (L & 3);
    const float* p1 = p0 + 8 * D;
#pragma unroll
    for (int ks = 0; ks < 4; ks++) {
        float2 v00 = *(const float2*)(p0 + 16 * ks);
        float2 v10 = *(const float2*)(p1 + 16 * ks);
        float2 v01 = *(const float2*)(p0 + 16 * ks + 8);
        float2 v11 = *(const float2*)(p1 + 16 * ks + 8);
        qa[ks][0] = packh2(v00.x * SCALE, v00.y * SCALE);
        qa[ks][1] = packh2(v10.x * SCALE, v10.y * SCALE);
        qa[ks][2] = packh2(v01.x * SCALE, v01.y * SCALE);
        qa[ks][3] = packh2(v11.x * SCALE, v11.y * SCALE);
    }
}

// ---------------- prep: fp32 -> fp16 for K and V ----------------
__global__ void prep16(const float* __restrict__ k, const float* __restrict__ v) {
    const int N4 = BH * S * D / 4;
    int i = blockIdx.x * blockDim.x + threadIdx.x;
    if (i >= N4) return;
    float4 b = ((const float4*)k)[i];
    float4 c = ((const float4*)v)[i];
    __half2* k2 = (__half2*)g_k16;
    __half2* v2 = (__half2*)g_v16;
    k2[2 * i]     = __floats2half2_rn(b.x, b.y);
    k2[2 * i + 1] = __floats2half2_rn(b.z, b.w);
    v2[2 * i]     = __floats2half2_rn(c.x, c.y);
    v2[2 * i + 1] = __floats2half2_rn(c.z, c.w);
}

// ---------------- main fused attention (2-loop, half2 exp, MMA row-sums) ----------------
__global__ __launch_bounds__(THREADS, 2)
void attn_main(const float* __restrict__ qf, const int* __restrict__ mask,
               float* __restrict__ out, float* __restrict__ attn)
{
    extern __shared__ char smem[];
    const uint32_t sb = su32(smem);
    const int tid = threadIdx.x;
    const int w   = tid >> 5;
    const int L   = tid & 31;
    const int q_  = L & 3;
    const int bh  = blockIdx.y;
    const int q0  = blockIdx.x * QT;      // A: rows q0.., B: rows q0+128..

    const float* qgA = qf + ((size_t)bh * S + q0) * D;
    const float* qgB = qgA + 128 * D;
    const __half* kg = g_k16 + (size_t)bh * S * D;
    const __half* vg = g_v16 + (size_t)bh * S * D;

    const uint32_t sK[2] = { sb + SM_K0, sb + SM_K1 };
    const uint32_t sV[2] = { sb + SM_V0, sb + SM_V1 };
    __half2* bh2 = (__half2*)(smem + SM_BIAS);

    // prologue: first K/V tile + half2 bias table (0 / -inf per column)
    load_tile(sK[0], kg, tid);
    load_tile(sV[0], vg, tid);
    CP_COMMIT();
    {
        const int* mp = mask + (size_t)(bh >> 4) * S;
        for (int i = tid; i < S / 2; i += THREADS) {
            uint32_t b = (mp[2 * i] ? 0u : 0xFC00u) |
                         ((mp[2 * i + 1] ? 0u : 0xFC00u) << 16);
            ((uint32_t*)bh2)[i] = b;
        }
    }

    const uint32_t ka_part = (L & 7) * RSB + (L >> 3) * 16;
    const uint32_t va_part = L * RSB;
    const int      c_base  = 2 * q_;

    // Q fragments for both halves, direct from fp32 global
    uint32_t qaA[4][4], qaB[4][4];
    load_q_frags(qaA, qgA + w * 16 * D, L);
    load_q_frags(qaB, qgB + w * 16 * D, L);

    CP_WAIT0();
    __syncthreads();

    float invA_lo, invA_hi, invB_lo, invB_hi;

    // ===== loop 1: QK_A + QK_B (shared LDSM) -> sums via ones-MMA + PV_A =====
    {
        float4 oc[8];
#pragma unroll
        for (int nb = 0; nb < 8; nb++) oc[nb] = make_float4(0.f, 0.f, 0.f, 0.f);
        float4 saccA = make_float4(0.f, 0.f, 0.f, 0.f);
        float4 saccB = make_float4(0.f, 0.f, 0.f, 0.f);

        for (int kt = 0; kt < NTILES; kt++) {
            const int cur = kt & 1;
            if (kt + 1 < NTILES) {
                load_tile(sK[cur ^ 1], kg + (size_t)(kt + 1) * NT * D, tid);
                load_tile(sV[cur ^ 1], vg + (size_t)(kt + 1) * NT * D, tid);
                CP_COMMIT();
            }
            const __half2* brow = bh2 + kt * (NT / 2);

#pragma unroll
            for (int kb2 = 0; kb2 < 4; kb2++) {
                uint32_t a16A[2][4], a16B[2][4];
#pragma unroll
                for (int i = 0; i < 4; i++) {
                    int nb = kb2 * 4 + i;
                    uint32_t kaddr = sK[cur] + nb * 8 * RSB + ka_part;
                    uint32_t b0, b1, b2, b3, b4, b5, b6, b7;
                    LDSM4(b0, b1, b2, b3, kaddr);
                    LDSM4(b4, b5, b6, b7, kaddr + 64);
                    __half2 bias2 = brow[nb * 4 + q_];
                    // A half
                    {
                        float4 cf = make_float4(0.f, 0.f, 0.f, 0.f);
                        mma_f16(cf, qaA[0], b0, b1);
                        mma_f16(cf, qaA[1], b2, b3);
                        mma_f16(cf, qaA[2], b4, b5);
                        mma_f16(cf, qaA[3], b6, b7);
                        a16A[i >> 1][(i & 1) * 2]     = exp2pair(cf.x, cf.y, bias2);
                        a16A[i >> 1][(i & 1) * 2 + 1] = exp2pair(cf.z, cf.w, bias2);
                    }
                    // B half
                    {
                        float4 cf = make_float4(0.f, 0.f, 0.f, 0.f);
                        mma_f16(cf, qaB[0], b0, b1);
                        mma_f16(cf, qaB[1], b2, b3);
                        mma_f16(cf, qaB[2], b4, b5);
                        mma_f16(cf, qaB[3], b6, b7);
                        a16B[i >> 1][(i & 1) * 2]     = exp2pair(cf.x, cf.y, bias2);
                        a16B[i >> 1][(i & 1) * 2 + 1] = exp2pair(cf.z, cf.w, bias2);
                    }
                }
                // row sums via ones-MMA (every lane ends with its rows' full sums)
                mma_f16(saccA, a16A[0], ONES2, ONES2);
                mma_f16(saccA, a16A[1], ONES2, ONES2);
                mma_f16(saccB, a16B[0], ONES2, ONES2);
                mma_f16(saccB, a16B[1], ONES2, ONES2);
                // PV_A
#pragma unroll
                for (int nbo = 0; nbo < 8; nbo++) {
                    uint32_t vaddr = sV[cur] + kb2 * 32 * RSB + nbo * 16 + va_part;
                    uint32_t v0, v1, v2, v3;
                    LDSM4T(v0, v1, v2, v3, vaddr);
                    mma_f16(oc[nbo], a16A[0], v0, v1);
                    mma_f16(oc[nbo], a16A[1], v2, v3);
                }
            }

            if (kt + 1 < NTILES) CP_WAIT0();
            __syncthreads();
        }

        invA_lo = 1.0f / saccA.x;
        invA_hi = 1.0f / saccA.z;
        invB_lo = 1.0f / saccB.x;
        invB_hi = 1.0f / saccB.z;

        // O_A write
        float* olo = out + ((size_t)bh * S + q0 + w * 16 + (L >> 2)) * D + c_base;
        float* ohi = olo + 8 * D;
#pragma unroll
        for (int nb = 0; nb < 8; nb++) {
            *(float2*)(olo + nb * 8) = make_float2(oc[nb].x * invA_lo, oc[nb].y * invA_lo);
            *(float2*)(ohi + nb * 8) = make_float2(oc[nb].z * invA_hi, oc[nb].w * invA_hi);
        }
    }

    // ===== loop 2: attn_A + attn_B writes + PV_B (shared K LDSM) =====
    {
        load_tile(sK[0], kg, tid);
        load_tile(sV[0], vg, tid);
        CP_COMMIT();
        CP_WAIT0();
        __syncthreads();

        float4 oc[8];
#pragma unroll
        for (int nb = 0; nb < 8; nb++) oc[nb] = make_float4(0.f, 0.f, 0.f, 0.f);

        float* aAlo = attn + ((size_t)bh * S + q0 + w * 16 + (L >> 2)) * S;
        float* aAhi = aAlo + 8 * (size_t)S;
        float* aBlo = attn + ((size_t)bh * S + q0 + 128 + w * 16 + (L >> 2)) * S;
        float* aBhi = aBlo + 8 * (size_t)S;

        for (int kt = 0; kt < NTILES; kt++) {
            const int cur = kt & 1;
            if (kt + 1 < NTILES) {
                load_tile(sK[cur ^ 1], kg + (size_t)(kt + 1) * NT * D, tid);
                load_tile(sV[cur ^ 1], vg + (size_t)(kt + 1) * NT * D, tid);
                CP_COMMIT();
            }
            const __half2* brow = bh2 + kt * (NT / 2);

#pragma unroll
            for (int kb2 = 0; kb2 < 4; kb2++) {
                uint32_t a16A[2][4], a16B[2][4];
#pragma unroll
                for (int i = 0; i < 4; i++) {
                    int nb = kb2 * 4 + i;
                    uint32_t kaddr = sK[cur] + nb * 8 * RSB + ka_part;
                    uint32_t b0, b1, b2, b3, b4, b5, b6, b7;
                    LDSM4(b0, b1, b2, b3, kaddr);
                    LDSM4(b4, b5, b6, b7, kaddr + 64);
                    __half2 bias2 = brow[nb * 4 + q_];
                    {
                        float4 cf = make_float4(0.f, 0.f, 0.f, 0.f);
                        mma_f16(cf, qaA[0], b0, b1);
                        mma_f16(cf, qaA[1], b2, b3);
                        mma_f16(cf, qaA[2], b4, b5);
                        mma_f16(cf, qaA[3], b6, b7);
                        a16A[i >> 1][(i & 1) * 2]     = exp2pair(cf.x, cf.y, bias2);
                        a16A[i >> 1][(i & 1) * 2 + 1] = exp2pair(cf.z, cf.w, bias2);
                    }
                    {
                        float4 cf = make_float4(0.f, 0.f, 0.f, 0.f);
                        mma_f16(cf, qaB[0], b0, b1);
                        mma_f16(cf, qaB[1], b2, b3);
                        mma_f16(cf, qaB[2], b4, b5);
                        mma_f16(cf, qaB[3], b6, b7);
                        a16B[i >> 1][(i & 1) * 2]     = exp2pair(cf.x, cf.y, bias2);
                        a16B[i >> 1][(i & 1) * 2 + 1] = exp2pair(cf.z, cf.w, bias2);
                    }
                }
                const int col = kt * NT + kb2 * 32 + 8 * q_;
                // attn_A write
                {
                    float2 flo[4], fhi[4];
#pragma unroll
                    for (int i = 0; i < 4; i++) {
                        float2 t = unpackh2(a16A[i >> 1][(i & 1) * 2]);
                        flo[i] = make_float2(t.x * invA_lo, t.y * invA_lo);
                        t = unpackh2(a16A[i >> 1][(i & 1) * 2 + 1]);
                        fhi[i] = make_float2(t.x * invA_hi, t.y * invA_hi);
                    }
                    quad_transpose_f2(flo, q_);
                    quad_transpose_f2(fhi, q_);
                    __stcs((float4*)(aAlo + col),
                           make_float4(flo[0].x, flo[0].y, flo[1].x, flo[1].y));
                    __stcs((float4*)(aAlo + col + 4),
                           make_float4(flo[2].x, flo[2].y, flo[3].x, flo[3].y));
                    __stcs((float4*)(aAhi + col),
                           make_float4(fhi[0].x, fhi[0].y, fhi[1].x, fhi[1].y));
                    __stcs((float4*)(aAhi + col + 4),
                           make_float4(fhi[2].x, fhi[2].y, fhi[3].x, fhi[3].y));
                }
                // attn_B write
                {
                    float2 flo[4], fhi[4];
#pragma unroll
                    for (int i = 0; i < 4; i++) {
                        float2 t = unpackh2(a16B[i >> 1][(i & 1) * 2]);
                        flo[i] = make_float2(t.x * invB_lo, t.y * invB_lo);
                        t = unpackh2(a16B[i >> 1][(i & 1) * 2 + 1]);
                        fhi[i] = make_float2(t.x * invB_hi, t.y * invB_hi);
                    }
                    quad_transpose_f2(flo, q_);
                    quad_transpose_f2(fhi, q_);
                    __stcs((float4*)(aBlo + col),
                           make_float4(flo[0].x, flo[0].y, flo[1].x, flo[1].y));
                    __stcs((float4*)(aBlo + col + 4),
                           make_float4(flo[2].x, flo[2].y, flo[3].x, flo[3].y));
                    __stcs((float4*)(aBhi + col),
                           make_float4(fhi[0].x, fhi[0].y, fhi[1].x, fhi[1].y));
                    __stcs((float4*)(aBhi + col + 4),
                           make_float4(fhi[2].x, fhi[2].y, fhi[3].x, fhi[3].y));
                }
                // PV_B
#pragma unroll
                for (int nbo = 0; nbo < 8; nbo++) {
                    uint32_t vaddr = sV[cur] + kb2 * 32 * RSB + nbo * 16 + va_part;
                    uint32_t v0, v1, v2, v3;
                    LDSM4T(v0, v1, v2, v3, vaddr);
                    mma_f16(oc[nbo], a16B[0], v0, v1);
                    mma_f16(oc[nbo], a16B[1], v2, v3);
                }
            }

            if (kt + 1 < NTILES) CP_WAIT0();
            __syncthreads();
        }

        // O_B write
        float* olo = out + ((size_t)bh * S + q0 + 128 + w * 16 + (L >> 2)) * D + c_base;
        float* ohi = olo + 8 * D;
#pragma unroll
        for (int nb = 0; nb < 8; nb++) {
            *(float2*)(olo + nb * 8) = make_float2(oc[nb].x * invB_lo, oc[nb].y * invB_lo);
            *(float2*)(ohi + nb * 8) = make_float2(oc[nb].z * invB_hi, oc[nb].w * invB_hi);
        }
    }
}

// ---------------- launch ----------------
extern "C" void kernel_launch(void* const* d_in, const int* in_sizes, int n_in,
                              void* d_out, int out_size)
{
    const float* q    = (const float*)d_in[0];
    const float* k    = (const float*)d_in[1];
    const float* v    = (const float*)d_in[2];
    const int*   mask = (const int*)  d_in[3];

    float* out  = (float*)d_out;
    float* attn = out + (size_t)BH * S * D;

    cudaFuncSetAttribute(attn_main, cudaFuncAttributeMaxDynamicSharedMemorySize, SMEM_SZ);

    const int N4 = BH * S * D / 4;
    prep16<<<(N4 + 255) / 256, 256>>>(k, v);
    attn_main<<<dim3(S / QT, BH), THREADS, SMEM_SZ>>>(q, mask, out, attn);
}